// round 17
// baseline (speedup 1.0000x reference)
// R17: R16 + (a) oyblk=3 warps 6-7 skip MMAs (outputs were 100% discarded),
//            (b) prep_x at 256 threads (halves serial iters per block).
#include <cuda_runtime.h>
#include <cuda_fp16.h>
#include <cstdint>

#define DINL __device__ __forceinline__

// ---------------- device scratch (no allocations allowed) -------------------
// x channel-last fp16: row = flat(b,x,y,z), 144 ci per row (288B).
// +1024 pad rows for window-shift overhang (lands in discarded outputs).
__device__ __align__(16) __half g_xh[(262144 + 1024) * 144];
// W rows: [(kx*3+kz)*9 + chunk*3 + ky][co32][ci64] = 2592 rows x 128B
__device__ __align__(16) __half g_bh[2592 * 64];

// ---------------- PTX helpers ----------------------------------------------
DINL uint32_t smem_u32(const void* p) {
    uint32_t a;
    asm("{ .reg .u64 t; cvta.to.shared.u64 t, %1; cvt.u32.u64 %0, t; }" : "=r"(a) : "l"(p));
    return a;
}
DINL void cp16(uint32_t s, const void* g) {
    asm volatile("cp.async.cg.shared.global [%0], [%1], 16;" :: "r"(s), "l"(g));
}
DINL void cp_commit() { asm volatile("cp.async.commit_group;"); }
DINL void cp_wait2()  { asm volatile("cp.async.wait_group 2;" ::: "memory"); }
DINL void cp_wait1()  { asm volatile("cp.async.wait_group 1;" ::: "memory"); }
DINL void cp_wait0()  { asm volatile("cp.async.wait_group 0;" ::: "memory"); }

DINL void ldm4(uint32_t& r0, uint32_t& r1, uint32_t& r2, uint32_t& r3, uint32_t a) {
    asm volatile("ldmatrix.sync.aligned.m8n8.x4.shared.b16 {%0,%1,%2,%3}, [%4];"
                 : "=r"(r0), "=r"(r1), "=r"(r2), "=r"(r3) : "r"(a));
}
DINL void mma16816(float& d0, float& d1, float& d2, float& d3,
                   uint32_t a0, uint32_t a1, uint32_t a2, uint32_t a3,
                   uint32_t b0, uint32_t b1) {
    asm volatile(
        "mma.sync.aligned.m16n8k16.row.col.f32.f16.f16.f32 "
        "{%0,%1,%2,%3}, {%4,%5,%6,%7}, {%8,%9}, {%0,%1,%2,%3};"
        : "+f"(d0), "+f"(d1), "+f"(d2), "+f"(d3)
        : "r"(a0), "r"(a1), "r"(a2), "r"(a3), "r"(b0), "r"(b1));
}

// ---------------- prep 1: x -> channel-last fp16 (256 threads) ---------------
__global__ void prep_x(const float* __restrict__ x) {
    __shared__ float t[144 * 33];
    int bid = blockIdx.x;                 // 8192 = 8b*32x*32y
    int b = bid >> 10, xx = (bid >> 5) & 31, y = bid & 31;
#pragma unroll 2
    for (int i = threadIdx.x; i < 144 * 32; i += 256) {
        int ci = i >> 5, z = i & 31;
        t[ci * 33 + z] = x[(size_t)(b * 144 + ci) * 32768 + xx * 1024 + y * 32 + z];
    }
    __syncthreads();
    size_t rb = ((((size_t)b * 32 + xx) * 32 + y) * 32) * 72;   // uint32 units
    uint32_t* oh = (uint32_t*)g_xh;
#pragma unroll 2
    for (int j = threadIdx.x; j < 32 * 72; j += 256) {
        int z = j / 72, cp = j % 72, ci = cp * 2;
        __half2 vh;
        vh.x = __float2half(t[ci * 33 + z]);
        vh.y = __float2half(t[(ci + 1) * 33 + z]);
        oh[rb + (size_t)z * 72 + cp] = *(uint32_t*)&vh;
    }
}

// ---------------- prep 2: W -> B rows fp16 ----------------------------------
__global__ void prep_w(const float* __restrict__ W) {
    int i = blockIdx.x * 256 + threadIdx.x;
    if (i >= 2592 * 64) return;
    int row = i >> 6, cil = i & 63;
    int co = row & 31, tt = row >> 5;
    int ky = tt % 3, chunk = (tt / 3) % 3, kxkz = tt / 9;
    int kx = kxkz / 3, kz = kxkz % 3;
    int ci = chunk * 64 + cil;
    float f = (ci < 144) ? W[(size_t)(co * 144 + ci) * 27 + kx * 9 + ky * 3 + kz] : 0.f;
    g_bh[i] = __float2half(f);
}

// ---------------- main: implicit GEMM, M=256, fp16 single-pass ---------------
// CTA: M=256 = 8oy x 32oz, N=32. 256 thr, 8 warps; warp w owns M [w*32,w*32+32).
// Grid 960 = 8b * 30ox * 4oyblk. oyblk=3 covers oy 24-31: warps 6-7 (oy 30,31)
// produce only discarded rows -> they skip the MMA section entirely.
// smem: A 2 x 41984 = 83968 | B 2 x 12288 = 24576 -> 108544 (106KB), occ 2.
static constexpr int A_SLOT = 328 * 128;            // 41984
static constexpr int OFF_B  = 2 * A_SLOT;           // 83968
static constexpr int B_SLOT = 96 * 128;             // 12288
static constexpr int SMEM_TOT = OFF_B + 2 * B_SLOT; // 108544

DINL void stage_A(int u, int b, int ox, int oy0, int tid, uint32_t dst) {
    int kx = u / 3, chunk = u % 3;
    int cgmax = (chunk < 2) ? 8 : 2;
    int cgsh  = (chunk < 2) ? 3 : 1;
    int f0 = ((b * 32 + ox + kx) * 32 + oy0) * 32;
    const char* gh = (const char*)g_xh + (size_t)f0 * 288 + chunk * 128;
    for (int idx = tid; idx < 328 * cgmax; idx += 256) {
        int row = idx >> cgsh, cg = idx & (cgmax - 1);
        cp16(dst + row * 128 + ((cg ^ (row & 7)) << 4),
             gh + (size_t)row * 288 + cg * 16);
    }
}
DINL void stage_B(int s, int tid, uint32_t dst) {
    int kx = s / 9, chunk = (s % 9) / 3, kz = s % 3;
    int cgmax = (chunk < 2) ? 8 : 2;
    int cgsh  = (chunk < 2) ? 3 : 1;
    int brow0 = ((kx * 3 + kz) * 9 + chunk * 3) * 32;
    const char* gh = (const char*)g_bh + (size_t)brow0 * 128;
    for (int idx = tid; idx < 96 * cgmax; idx += 256) {
        int row = idx >> cgsh, cg = idx & (cgmax - 1);
        cp16(dst + row * 128 + ((cg ^ (row & 7)) << 4),
             gh + (size_t)row * 128 + cg * 16);
    }
}

__global__ __launch_bounds__(256, 2)
void conv_mma(float* __restrict__ out) {
    extern __shared__ char smem[];
    uint32_t sb = smem_u32(smem);
    int tid = threadIdx.x, w = tid >> 5, lane = tid & 31;

    int bid = blockIdx.x;                       // 960 = 8b * 30ox * 4oyblk
    int b = bid / 120, r = bid % 120, ox = r / 4, oyblk = r % 4;
    int oy0 = oyblk * 8;
    // oyblk==3: warps 6,7 own Mrows 192-255 -> oy 30,31 -> all outputs discarded
    bool active = !(oyblk == 3 && w >= 6);

    // canonical ldmatrix.x4 lane geometry (proven R11/R13/R16)
    int lrow = (lane & 7) + (((lane >> 3) & 1) << 3);
    int lblk = lane >> 4;

    float c[2][4][4];
#pragma unroll
    for (int m = 0; m < 2; m++)
#pragma unroll
        for (int n = 0; n < 4; n++)
#pragma unroll
            for (int j = 0; j < 4; j++) c[m][n][j] = 0.f;

    stage_A(0, b, ox, oy0, tid, sb);
    cp_commit();
    stage_B(0, tid, sb + OFF_B);
    cp_commit();

    for (int s = 0; s < 27; s++) {
        int u = s / 3, kz = s % 3, chunk = u % 3;
        uint32_t abuf = sb + (u & 1) * A_SLOT;
        uint32_t bbuf = sb + OFF_B + (s & 1) * B_SLOT;

        __syncthreads();
        int n_new = 0;
        if (kz == 0 && u + 1 < 9) {
            stage_A(u + 1, b, ox, oy0, tid, sb + ((u + 1) & 1) * A_SLOT);
            cp_commit(); n_new++;
        }
        if (s + 1 < 27) {
            stage_B(s + 1, tid, sb + OFF_B + ((s + 1) & 1) * B_SLOT);
            cp_commit(); n_new++;
        }
        if (n_new == 2) cp_wait2(); else if (n_new == 1) cp_wait1(); else cp_wait0();
        __syncthreads();

        if (active) {
            int ksteps = (chunk < 2) ? 4 : 1;
            uint32_t csA = (uint32_t)((lane + kz) & 7);
            uint32_t csB = (uint32_t)(lane & 7);
#pragma unroll 1
            for (int ks = 0; ks < ksteps; ks++) {
                uint32_t colA = (uint32_t)(((ks * 2 + lblk) ^ csA) << 4);
                uint32_t colB = (uint32_t)(((ks * 2 + lblk) ^ csB) << 4);
#pragma unroll
                for (int ky = 0; ky < 3; ky++) {
                    uint32_t br0 = (uint32_t)(ky * 32 + lrow) * 128;
                    uint32_t br1 = (uint32_t)(ky * 32 + 16 + lrow) * 128;
                    uint32_t bh0, bh1, bh2, bh3, bh4, bh5, bh6, bh7;
                    ldm4(bh0, bh1, bh2, bh3, bbuf + br0 + colB);
                    ldm4(bh4, bh5, bh6, bh7, bbuf + br1 + colB);
#pragma unroll
                    for (int m = 0; m < 2; m++) {
                        uint32_t arow =
                            (uint32_t)(w * 32 + m * 16 + ky * 32 + kz + lrow) * 128;
                        uint32_t a0, a1, a2, a3;
                        ldm4(a0, a1, a2, a3, abuf + arow + colA);
                        mma16816(c[m][0][0], c[m][0][1], c[m][0][2], c[m][0][3], a0, a1, a2, a3, bh0, bh2);
                        mma16816(c[m][1][0], c[m][1][1], c[m][1][2], c[m][1][3], a0, a1, a2, a3, bh1, bh3);
                        mma16816(c[m][2][0], c[m][2][1], c[m][2][2], c[m][2][3], a0, a1, a2, a3, bh4, bh6);
                        mma16816(c[m][3][0], c[m][3][1], c[m][3][2], c[m][3][3], a0, a1, a2, a3, bh5, bh7);
                    }
                }
            }
        }
    }

    // ---- epilogue: Mrow = w*32 + m*16 + rr(+8); oy = oy0 + Mrow/32, oz = Mrow%32
    int rr = lane >> 2;
    int nb = (lane & 3) * 2;
#pragma unroll
    for (int m = 0; m < 2; m++)
#pragma unroll
        for (int half = 0; half < 2; half++) {
            int Mrow = w * 32 + m * 16 + rr + half * 8;
            int oy = oy0 + (Mrow >> 5);
            int oz = Mrow & 31;
            if (oy < 30 && oz < 30) {
                float* ob = out + (size_t)b * 32 * 27000 + ox * 900 + oy * 30 + oz;
#pragma unroll
                for (int nt = 0; nt < 4; nt++) {
                    int n = nt * 8 + nb;
                    ob[(size_t)n * 27000]       = c[m][nt][half * 2];
                    ob[(size_t)(n + 1) * 27000] = c[m][nt][half * 2 + 1];
                }
            }
        }
}

// ---------------- host ------------------------------------------------------
extern "C" void kernel_launch(void* const* d_in, const int* in_sizes, int n_in,
                              void* d_out, int out_size) {
    const float* x = (const float*)d_in[0];
    const float* W = (const float*)d_in[1];
    if (n_in >= 2 && in_sizes[0] == 124416) { const float* t = x; x = W; W = t; }
    float* out = (float*)d_out;

    cudaFuncSetAttribute(conv_mma, cudaFuncAttributeMaxDynamicSharedMemorySize, SMEM_TOT);

    prep_x<<<8192, 256>>>(x);
    prep_w<<<(2592 * 64 + 255) / 256, 256>>>(W);
    conv_mma<<<960, 256, SMEM_TOT>>>(out);
}